// round 2
// baseline (speedup 1.0000x reference)
#include <cuda_runtime.h>

#define BB 4
#define NN 40960
#define KK 16
#define DD 64
#define HH 32
#define NPTS (BB * NN)
#define EPSV 1e-5f

typedef unsigned long long ull;

// ---------- packed f32x2 helpers ----------
__device__ __forceinline__ ull ffma2(ull a, ull b, ull c) {
    ull d;
    asm("fma.rn.f32x2 %0, %1, %2, %3;" : "=l"(d) : "l"(a), "l"(b), "l"(c));
    return d;
}
__device__ __forceinline__ ull pack2(float lo, float hi) {
    ull d;
    asm("mov.b64 %0, {%1, %2};" : "=l"(d) : "f"(lo), "f"(hi));
    return d;
}
__device__ __forceinline__ void unpack2(ull v, float& lo, float& hi) {
    asm("mov.b64 {%0, %1}, %2;" : "=f"(lo), "=f"(hi) : "l"(v));
}

// ---------- folded weights (BN scale pre-multiplied), packed over out-channel pairs ----------
__device__ ull dW2P[DD][HH / 2];        // [c][hp] = (s2*W2[2hp][c], s2*W2[2hp+1][c])
__device__ ull dW3AP[HH][HH / 2];       // W3[:, 0:32]  (applies to gathered f)
__device__ ull dW3BP[HH][HH / 2];       // W3[:, 32:64] (applies to f_xyz)
__device__ ull dW4P[2 * HH][DD / 2];    // [c][dp]
__device__ float dM0[HH * 3];           // s1*(W1[:,1:4]+W1[:,4:7])  (center terms)
__device__ float dM1[HH * 3];           // s1*(W1[:,7:10]-W1[:,1:4]) (neighbor terms)
__device__ float dW1D[HH];              // s1*W1[:,0] (distance)
__device__ float dB1[HH], dB2[HH], dB3[HH], dB4[DD];
__device__ int dIdx64;                  // 1 if neigh_idx is int64, 0 if int32

// ---------- scratch (static: no allocation allowed) ----------
__device__ float dF[NPTS * HH];    // f per point (post-ReLU)
__device__ float dHP[NPTS * HH];   // hpre = M1 @ xyz  (gathered per neighbor)
__device__ float dG[NPTS * HH];    // g'   = s3*(W3a@f)+b3 (gathered per neighbor)

// ================== prep: fold BN scales into weights, build packed layouts ==================
__global__ void prep_kernel(const float* __restrict__ W1, const float* __restrict__ W2,
                            const float* __restrict__ W3, const float* __restrict__ W4,
                            const float* __restrict__ g1, const float* __restrict__ b1,
                            const float* __restrict__ g2, const float* __restrict__ b2,
                            const float* __restrict__ g3, const float* __restrict__ b3,
                            const float* __restrict__ g4, const float* __restrict__ b4) {
    int t = threadIdx.x;
    float inv = rsqrtf(1.0f + EPSV);
    for (int i = t; i < DD * (HH / 2); i += blockDim.x) {
        int c = i >> 4, hp = i & 15;
        dW2P[c][hp] = pack2(g2[2 * hp] * inv * W2[(2 * hp) * DD + c],
                            g2[2 * hp + 1] * inv * W2[(2 * hp + 1) * DD + c]);
    }
    for (int i = t; i < HH * (HH / 2); i += blockDim.x) {
        int c = i >> 4, hp = i & 15;
        float s0 = g3[2 * hp] * inv, s1 = g3[2 * hp + 1] * inv;
        dW3AP[c][hp] = pack2(s0 * W3[(2 * hp) * (2 * HH) + c],
                             s1 * W3[(2 * hp + 1) * (2 * HH) + c]);
        dW3BP[c][hp] = pack2(s0 * W3[(2 * hp) * (2 * HH) + HH + c],
                             s1 * W3[(2 * hp + 1) * (2 * HH) + HH + c]);
    }
    for (int i = t; i < (2 * HH) * (DD / 2); i += blockDim.x) {
        int c = i >> 5, dp = i & 31;
        dW4P[c][dp] = pack2(g4[2 * dp] * inv * W4[(2 * dp) * (2 * HH) + c],
                            g4[2 * dp + 1] * inv * W4[(2 * dp + 1) * (2 * HH) + c]);
    }
    for (int h = t; h < HH; h += blockDim.x) {
        float s = g1[h] * inv;
        dW1D[h] = s * W1[h * 10 + 0];
        for (int i = 0; i < 3; i++) {
            dM0[h * 3 + i] = s * (W1[h * 10 + 1 + i] + W1[h * 10 + 4 + i]);
            dM1[h * 3 + i] = s * (W1[h * 10 + 7 + i] - W1[h * 10 + 1 + i]);
        }
        dB1[h] = b1[h];
        dB2[h] = b2[h];
        dB3[h] = b3[h];
    }
    for (int d = t; d < DD; d += blockDim.x) dB4[d] = b4[d];
}

// ================== detect int64 vs int32 neigh_idx (high 32-bit words all zero?) ==================
__global__ void detect_kernel(const unsigned int* __restrict__ w) {
    __shared__ int sBad;
    if (threadIdx.x == 0) sBad = 0;
    __syncthreads();
    unsigned int acc = 0;
    for (int i = threadIdx.x; i < 2048; i += blockDim.x) acc |= w[2 * i + 1];
    if (acc) atomicOr(&sBad, 1);
    __syncthreads();
    if (threadIdx.x == 0) dIdx64 = (sBad == 0) ? 1 : 0;
}

// ================== pass 1: per-point f, g'=W3a@f+b3, hpre=M1@xyz ==================
__global__ void __launch_bounds__(128) pass1_kernel(const float* __restrict__ feat,
                                                    const float* __restrict__ xyz) {
    __shared__ ull sW2[DD][HH / 2];
    __shared__ ull sW3A[HH][HH / 2];
    __shared__ float sM1[HH * 3], sB2[HH], sB3[HH];
    int tid = threadIdx.x;
    for (int i = tid; i < DD * (HH / 2); i += 128) ((ull*)sW2)[i] = ((ull*)dW2P)[i];
    for (int i = tid; i < HH * (HH / 2); i += 128) ((ull*)sW3A)[i] = ((ull*)dW3AP)[i];
    for (int i = tid; i < HH * 3; i += 128) sM1[i] = dM1[i];
    if (tid < HH) { sB2[tid] = dB2[tid]; sB3[tid] = dB3[tid]; }
    __syncthreads();

    int p = blockIdx.x * 128 + tid;       // p = b*NN + n
    int b = p / NN;
    int n = p - b * NN;

    // f = relu(W2' @ feature_col + b2)
    ull acc[HH / 2];
#pragma unroll
    for (int hp = 0; hp < 16; hp++) acc[hp] = 0ull;
    const float* fp = feat + (size_t)b * DD * NN + n;
#pragma unroll
    for (int c = 0; c < DD; c++) {
        float x = fp[(size_t)c * NN];
        ull xd = pack2(x, x);
#pragma unroll
        for (int hp = 0; hp < 16; hp++) acc[hp] = ffma2(sW2[c][hp], xd, acc[hp]);
    }
    float f[HH];
#pragma unroll
    for (int hp = 0; hp < 16; hp++) {
        float lo, hi;
        unpack2(acc[hp], lo, hi);
        f[2 * hp] = fmaxf(lo + sB2[2 * hp], 0.0f);
        f[2 * hp + 1] = fmaxf(hi + sB2[2 * hp + 1], 0.0f);
    }
    float* Frow = dF + (size_t)p * HH;
#pragma unroll
    for (int q = 0; q < 8; q++)
        ((float4*)Frow)[q] = make_float4(f[4 * q], f[4 * q + 1], f[4 * q + 2], f[4 * q + 3]);

    // g' = s3*(W3a @ f) + b3
#pragma unroll
    for (int hp = 0; hp < 16; hp++) acc[hp] = pack2(sB3[2 * hp], sB3[2 * hp + 1]);
#pragma unroll
    for (int c = 0; c < HH; c++) {
        ull xd = pack2(f[c], f[c]);
#pragma unroll
        for (int hp = 0; hp < 16; hp++) acc[hp] = ffma2(sW3A[c][hp], xd, acc[hp]);
    }
    ull* Grow = (ull*)(dG + (size_t)p * HH);
#pragma unroll
    for (int hp = 0; hp < 16; hp++) Grow[hp] = acc[hp];

    // hpre = M1 @ xyz[p]
    const float* xp = xyz + (size_t)p * 3;
    float x0 = xp[0], y0 = xp[1], z0 = xp[2];
    float hpre[HH];
#pragma unroll
    for (int h = 0; h < HH; h++)
        hpre[h] = sM1[h * 3] * x0 + sM1[h * 3 + 1] * y0 + sM1[h * 3 + 2] * z0;
    float* Hrow = dHP + (size_t)p * HH;
#pragma unroll
    for (int q = 0; q < 8; q++)
        ((float4*)Hrow)[q] = make_float4(hpre[4 * q], hpre[4 * q + 1], hpre[4 * q + 2], hpre[4 * q + 3]);
}

// ================== pass 2: per-point neighbor loop + W3b matvec + max + W4 ==================
__global__ void __launch_bounds__(128) pass2_kernel(const float* __restrict__ xyz,
                                                    const unsigned int* __restrict__ idxw,
                                                    float* __restrict__ out) {
    __shared__ ull sW3B[HH][HH / 2];     // 4 KB
    __shared__ ull sW4[2 * HH][DD / 2];  // 16 KB
    __shared__ float sM0[HH * 3], sW1D[HH], sB1[HH], sB4[DD];
    int tid = threadIdx.x;
    for (int i = tid; i < HH * (HH / 2); i += 128) ((ull*)sW3B)[i] = ((ull*)dW3BP)[i];
    for (int i = tid; i < 2 * HH * (DD / 2); i += 128) ((ull*)sW4)[i] = ((ull*)dW4P)[i];
    for (int i = tid; i < HH * 3; i += 128) sM0[i] = dM0[i];
    if (tid < HH) { sW1D[tid] = dW1D[tid]; sB1[tid] = dB1[tid]; }
    if (tid < DD) sB4[tid] = dB4[tid];
    __syncthreads();

    int p = blockIdx.x * 128 + tid;  // p = b*NN + n
    int b = p / NN;
    int n = p - b * NN;
    int shift = dIdx64;  // 1 -> int64 indices, read low words at stride 2

    const float* xp = xyz + (size_t)p * 3;
    float x0 = xp[0], y0 = xp[1], z0 = xp[2];
    float base[HH];
#pragma unroll
    for (int h = 0; h < HH; h++)
        base[h] = sB1[h] + sM0[h * 3] * x0 + sM0[h * 3 + 1] * y0 + sM0[h * 3 + 2] * z0;

    float fc[HH];
#pragma unroll
    for (int h = 0; h < HH; h++) fc[h] = -3.4e38f;

    unsigned int ib = (unsigned int)p * KK;

#pragma unroll 1
    for (int k = 0; k < KK; k++) {
        int j = (int)idxw[(size_t)(ib + k) << shift];
        size_t rj = (size_t)b * NN + j;
        const float* xj = xyz + rj * 3;
        float dx = x0 - xj[0], dy = y0 - xj[1], dz = z0 - xj[2];
        float dis = sqrtf(dx * dx + dy * dy + dz * dz);

        const float4* hp4 = (const float4*)(dHP + rj * HH);
        const ulonglong2* gg = (const ulonglong2*)(dG + rj * HH);
        float hpre[HH];
#pragma unroll
        for (int q = 0; q < 8; q++) {
            float4 v = hp4[q];
            hpre[4 * q] = v.x; hpre[4 * q + 1] = v.y; hpre[4 * q + 2] = v.z; hpre[4 * q + 3] = v.w;
        }
        ull acc[16];
#pragma unroll
        for (int q = 0; q < 8; q++) {
            ulonglong2 v = gg[q];
            acc[2 * q] = v.x; acc[2 * q + 1] = v.y;
        }
#pragma unroll
        for (int c = 0; c < HH; c++) {
            float fx = fmaxf(fmaf(sW1D[c], dis, base[c] + hpre[c]), 0.0f);
            ull fxd = pack2(fx, fx);
#pragma unroll
            for (int hp = 0; hp < 16; hp++) acc[hp] = ffma2(sW3B[c][hp], fxd, acc[hp]);
        }
#pragma unroll
        for (int hp = 0; hp < 16; hp++) {
            float lo, hi;
            unpack2(acc[hp], lo, hi);
            fc[2 * hp] = fmaxf(fc[2 * hp], lo);
            fc[2 * hp + 1] = fmaxf(fc[2 * hp + 1], hi);
        }
    }
    // relu(max) == max(relu) since relu is monotone
#pragma unroll
    for (int h = 0; h < HH; h++) fc[h] = fmaxf(fc[h], 0.0f);

    // final: out = relu(W4' @ [fc; f] + b4)
    float fv[HH];
    const float4* Fr = (const float4*)(dF + (size_t)p * HH);
#pragma unroll
    for (int q = 0; q < 8; q++) {
        float4 v = Fr[q];
        fv[4 * q] = v.x; fv[4 * q + 1] = v.y; fv[4 * q + 2] = v.z; fv[4 * q + 3] = v.w;
    }
    ull acco[DD / 2];
#pragma unroll
    for (int dp = 0; dp < 32; dp++) acco[dp] = 0ull;
#pragma unroll
    for (int c = 0; c < HH; c++) {
        ull xd = pack2(fc[c], fc[c]);
#pragma unroll
        for (int dp = 0; dp < 32; dp++) acco[dp] = ffma2(sW4[c][dp], xd, acco[dp]);
    }
#pragma unroll
    for (int c = 0; c < HH; c++) {
        ull xd = pack2(fv[c], fv[c]);
#pragma unroll
        for (int dp = 0; dp < 32; dp++) acco[dp] = ffma2(sW4[HH + c][dp], xd, acco[dp]);
    }
    float* op = out + (size_t)b * DD * NN + n;
#pragma unroll
    for (int dp = 0; dp < 32; dp++) {
        float lo, hi;
        unpack2(acco[dp], lo, hi);
        op[(size_t)(2 * dp) * NN] = fmaxf(lo + sB4[2 * dp], 0.0f);
        op[(size_t)(2 * dp + 1) * NN] = fmaxf(hi + sB4[2 * dp + 1], 0.0f);
    }
}

// ================== launch ==================
extern "C" void kernel_launch(void* const* d_in, const int* in_sizes, int n_in,
                              void* d_out, int out_size) {
    const float *feat, *xyz, *W1, *W2, *W3, *W4;
    const float *g1, *b1, *g2, *b2, *g3, *b3, *g4, *b4;
    const void* idx;
    if (n_in >= 3 && in_sizes[2] == 320) {
        // reference-signature order: feature, xyz, W1,g1,b1, W2,g2,b2, W3,g3,b3, W4,g4,b4, neigh_idx
        feat = (const float*)d_in[0];  xyz = (const float*)d_in[1];
        W1 = (const float*)d_in[2];    g1 = (const float*)d_in[3];  b1 = (const float*)d_in[4];
        W2 = (const float*)d_in[5];    g2 = (const float*)d_in[6];  b2 = (const float*)d_in[7];
        W3 = (const float*)d_in[8];    g3 = (const float*)d_in[9];  b3 = (const float*)d_in[10];
        W4 = (const float*)d_in[11];   g4 = (const float*)d_in[12]; b4 = (const float*)d_in[13];
        idx = d_in[14];
    } else {
        // setup_inputs dict order: feature, xyz, neigh_idx, W1..W4, g1,b1,g2,b2,g3,b3,g4,b4
        feat = (const float*)d_in[0];  xyz = (const float*)d_in[1];  idx = d_in[2];
        W1 = (const float*)d_in[3];    W2 = (const float*)d_in[4];
        W3 = (const float*)d_in[5];    W4 = (const float*)d_in[6];
        g1 = (const float*)d_in[7];    b1 = (const float*)d_in[8];
        g2 = (const float*)d_in[9];    b2 = (const float*)d_in[10];
        g3 = (const float*)d_in[11];   b3 = (const float*)d_in[12];
        g4 = (const float*)d_in[13];   b4 = (const float*)d_in[14];
    }
    prep_kernel<<<1, 256>>>(W1, W2, W3, W4, g1, b1, g2, b2, g3, b3, g4, b4);
    detect_kernel<<<1, 256>>>((const unsigned int*)idx);
    pass1_kernel<<<NPTS / 128, 128>>>(feat, xyz);
    pass2_kernel<<<NPTS / 128, 128>>>(xyz, (const unsigned int*)idx, (float*)d_out);
}

// round 3
// speedup vs baseline: 5.5384x; 5.5384x over previous
#include <cuda_runtime.h>
#include <float.h>

#define BB 4
#define NN 40960
#define KK 16
#define DD 64
#define HH 32
#define NPTS (BB * NN)
#define EPSV 1e-5f

typedef unsigned long long ull;

// ---------- packed f32x2 helpers ----------
__device__ __forceinline__ ull ffma2(ull a, ull b, ull c) {
    ull d;
    asm("fma.rn.f32x2 %0, %1, %2, %3;" : "=l"(d) : "l"(a), "l"(b), "l"(c));
    return d;
}
__device__ __forceinline__ ull pack2(float lo, float hi) {
    ull d;
    asm("mov.b64 %0, {%1, %2};" : "=l"(d) : "f"(lo), "f"(hi));
    return d;
}
__device__ __forceinline__ void unpack2(ull v, float& lo, float& hi) {
    asm("mov.b64 {%0, %1}, %2;" : "=f"(lo), "=f"(hi) : "l"(v));
}

// ---------- folded weights (BN scale pre-multiplied), packed over out-channel pairs ----------
__device__ ull dW2P[DD][HH / 2];        // [c][hp]
__device__ ull dW3AP[HH][HH / 2];       // W3[:, 0:32]  (applies to gathered f)
__device__ ull dW3BP[HH][HH / 2];       // W3[:, 32:64] (applies to f_xyz)
__device__ ull dW4P[2 * HH][DD / 2];    // [c][dp]
__device__ float dM0[HH * 3];           // s1*(W1[:,1:4]+W1[:,4:7])  (center terms)
__device__ float dM1[HH * 3];           // s1*(W1[:,7:10]-W1[:,1:4]) (neighbor terms)
__device__ float dW1D[HH];              // s1*W1[:,0] (distance)
__device__ float dB1[HH], dB2[HH], dB3[HH], dB4[DD];
__device__ int dIdx64;                  // 1 if neigh_idx is int64, 0 if int32

// ---------- scratch ----------
__device__ float dF[NPTS * HH];     // f per point (post-ReLU)
__device__ float dRow[NPTS * 64];   // merged row: [0:32]=hpre (M1@xyz), [32:64]=G (W3a@f+b3)
__device__ float dFC[NPTS * HH];    // max-pooled f_concat (post-ReLU)
__device__ float4 dXYZ4[NPTS];      // (x, y, z, 0)

// ================== prep ==================
__global__ void prep_kernel(const float* __restrict__ W1, const float* __restrict__ W2,
                            const float* __restrict__ W3, const float* __restrict__ W4,
                            const float* __restrict__ g1, const float* __restrict__ b1,
                            const float* __restrict__ g2, const float* __restrict__ b2,
                            const float* __restrict__ g3, const float* __restrict__ b3,
                            const float* __restrict__ g4, const float* __restrict__ b4) {
    int t = threadIdx.x;
    float inv = rsqrtf(1.0f + EPSV);
    for (int i = t; i < DD * (HH / 2); i += blockDim.x) {
        int c = i >> 4, hp = i & 15;
        dW2P[c][hp] = pack2(g2[2 * hp] * inv * W2[(2 * hp) * DD + c],
                            g2[2 * hp + 1] * inv * W2[(2 * hp + 1) * DD + c]);
    }
    for (int i = t; i < HH * (HH / 2); i += blockDim.x) {
        int c = i >> 4, hp = i & 15;
        float s0 = g3[2 * hp] * inv, s1 = g3[2 * hp + 1] * inv;
        dW3AP[c][hp] = pack2(s0 * W3[(2 * hp) * (2 * HH) + c],
                             s1 * W3[(2 * hp + 1) * (2 * HH) + c]);
        dW3BP[c][hp] = pack2(s0 * W3[(2 * hp) * (2 * HH) + HH + c],
                             s1 * W3[(2 * hp + 1) * (2 * HH) + HH + c]);
    }
    for (int i = t; i < (2 * HH) * (DD / 2); i += blockDim.x) {
        int c = i >> 5, dp = i & 31;
        dW4P[c][dp] = pack2(g4[2 * dp] * inv * W4[(2 * dp) * (2 * HH) + c],
                            g4[2 * dp + 1] * inv * W4[(2 * dp + 1) * (2 * HH) + c]);
    }
    for (int h = t; h < HH; h += blockDim.x) {
        float s = g1[h] * inv;
        dW1D[h] = s * W1[h * 10 + 0];
        for (int i = 0; i < 3; i++) {
            dM0[h * 3 + i] = s * (W1[h * 10 + 1 + i] + W1[h * 10 + 4 + i]);
            dM1[h * 3 + i] = s * (W1[h * 10 + 7 + i] - W1[h * 10 + 1 + i]);
        }
        dB1[h] = b1[h];
        dB2[h] = b2[h];
        dB3[h] = b3[h];
    }
    for (int d = t; d < DD; d += blockDim.x) dB4[d] = b4[d];
}

// ================== detect int64 vs int32 neigh_idx ==================
__global__ void detect_kernel(const unsigned int* __restrict__ w) {
    __shared__ int sBad;
    if (threadIdx.x == 0) sBad = 0;
    __syncthreads();
    unsigned int acc = 0;
    for (int i = threadIdx.x; i < 2048; i += blockDim.x) acc |= w[2 * i + 1];
    if (acc) atomicOr(&sBad, 1);
    __syncthreads();
    if (threadIdx.x == 0) dIdx64 = (sBad == 0) ? 1 : 0;
}

// ================== pass 1: per-point f, merged row (hpre | G), xyz4 ==================
__global__ void __launch_bounds__(128) pass1_kernel(const float* __restrict__ feat,
                                                    const float* __restrict__ xyz) {
    __shared__ ull sW2[DD][HH / 2];
    __shared__ ull sW3A[HH][HH / 2];
    __shared__ float sM1[HH * 3], sB2[HH], sB3[HH];
    int tid = threadIdx.x;
    for (int i = tid; i < DD * (HH / 2); i += 128) ((ull*)sW2)[i] = ((ull*)dW2P)[i];
    for (int i = tid; i < HH * (HH / 2); i += 128) ((ull*)sW3A)[i] = ((ull*)dW3AP)[i];
    for (int i = tid; i < HH * 3; i += 128) sM1[i] = dM1[i];
    if (tid < HH) { sB2[tid] = dB2[tid]; sB3[tid] = dB3[tid]; }
    __syncthreads();

    int p = blockIdx.x * 128 + tid;
    int b = p / NN;
    int n = p - b * NN;

    // f = relu(W2' @ feature_col + b2)
    ull acc[HH / 2];
#pragma unroll
    for (int hp = 0; hp < 16; hp++) acc[hp] = 0ull;
    const float* fp = feat + (size_t)b * DD * NN + n;
#pragma unroll
    for (int c = 0; c < DD; c++) {
        float x = fp[(size_t)c * NN];
        ull xd = pack2(x, x);
#pragma unroll
        for (int hp = 0; hp < 16; hp++) acc[hp] = ffma2(sW2[c][hp], xd, acc[hp]);
    }
    float f[HH];
#pragma unroll
    for (int hp = 0; hp < 16; hp++) {
        float lo, hi;
        unpack2(acc[hp], lo, hi);
        f[2 * hp] = fmaxf(lo + sB2[2 * hp], 0.0f);
        f[2 * hp + 1] = fmaxf(hi + sB2[2 * hp + 1], 0.0f);
    }
    float* Frow = dF + (size_t)p * HH;
#pragma unroll
    for (int q = 0; q < 8; q++)
        ((float4*)Frow)[q] = make_float4(f[4 * q], f[4 * q + 1], f[4 * q + 2], f[4 * q + 3]);

    // G = s3*(W3a @ f) + b3  -> dRow[p][32:64]
#pragma unroll
    for (int hp = 0; hp < 16; hp++) acc[hp] = pack2(sB3[2 * hp], sB3[2 * hp + 1]);
#pragma unroll
    for (int c = 0; c < HH; c++) {
        ull xd = pack2(f[c], f[c]);
#pragma unroll
        for (int hp = 0; hp < 16; hp++) acc[hp] = ffma2(sW3A[c][hp], xd, acc[hp]);
    }
    ull* Grow = (ull*)(dRow + (size_t)p * 64 + 32);
#pragma unroll
    for (int hp = 0; hp < 16; hp++) Grow[hp] = acc[hp];

    // hpre = M1 @ xyz[p] -> dRow[p][0:32]
    const float* xp = xyz + (size_t)p * 3;
    float x0 = xp[0], y0 = xp[1], z0 = xp[2];
    float* Hrow = dRow + (size_t)p * 64;
#pragma unroll
    for (int q = 0; q < 8; q++) {
        float v[4];
#pragma unroll
        for (int e = 0; e < 4; e++) {
            int h = 4 * q + e;
            v[e] = sM1[h * 3] * x0 + sM1[h * 3 + 1] * y0 + sM1[h * 3 + 2] * z0;
        }
        ((float4*)Hrow)[q] = make_float4(v[0], v[1], v[2], v[3]);
    }
    dXYZ4[p] = make_float4(x0, y0, z0, 0.0f);
}

// ================== pass 2: gather + W3b matvec + max-pool -> dFC ==================
__global__ void __launch_bounds__(128, 4) pass2_kernel(const unsigned int* __restrict__ idxw) {
    __shared__ ulonglong2 sW3B2[HH][8];      // 4 KB  (pairs of hp-pairs)
    __shared__ float sStage[4 * 32 * 68];    // 34816 B (per-warp gather stage, padded rows)
    __shared__ int sIdx[128 * 17];           // 8704 B (block's neighbor indices, padded)
    __shared__ float sM0[HH * 3], sW1D[HH], sB1[HH];
    int tid = threadIdx.x;
    for (int i = tid; i < HH * 8; i += 128) {
        int c = i >> 3, hq = i & 7;
        const ull* src = &dW3BP[c][2 * hq];
        sW3B2[c][hq] = make_ulonglong2(src[0], src[1]);
    }
    for (int i = tid; i < HH * 3; i += 128) sM0[i] = dM0[i];
    if (tid < HH) { sW1D[tid] = dW1D[tid]; sB1[tid] = dB1[tid]; }

    // stage indices for the whole block (coalesced), narrowing int64->int32 if needed
    int shift = dIdx64;
    {
        unsigned int gbase = (unsigned int)blockIdx.x * 2048u;
        for (int i = tid; i < 2048; i += 128) {
            unsigned int w = idxw[(size_t)(gbase + i) << shift];
            sIdx[(i >> 4) * 17 + (i & 15)] = (int)w;
        }
    }
    __syncthreads();

    int p = blockIdx.x * 128 + tid;
    int b = p / NN;
    int lane = tid & 31;
    int warp = tid >> 5;
    float* sw = sStage + warp * (32 * 68);

    float4 xc = dXYZ4[p];
    float x0 = xc.x, y0 = xc.y, z0 = xc.z;
    float base[HH];
#pragma unroll
    for (int h = 0; h < HH; h++)
        base[h] = sB1[h] + sM0[h * 3] * x0 + sM0[h * 3 + 1] * y0 + sM0[h * 3 + 2] * z0;

    float fc[HH];
#pragma unroll
    for (int h = 0; h < HH; h++) fc[h] = -FLT_MAX;

    const float4* rowF4 = (const float4*)dRow;
    int bBase = b * NN;

#pragma unroll 1
    for (int k = 0; k < KK; k++) {
        int j = sIdx[tid * 17 + k];
        int rj = bBase + j;

        // --- warp-cooperative stage of 32 neighbor rows (64 floats each) ---
        __syncwarp();
#pragma unroll
        for (int i = 0; i < 16; i++) {
            int src = 2 * i + (lane >> 4);
            int rs = __shfl_sync(0xffffffffu, rj, src);
            int e = lane & 15;
            float4 v = rowF4[(size_t)rs * 16 + e];
            *(float4*)(sw + src * 68 + e * 4) = v;
        }
        __syncwarp();

        // --- distance ---
        float4 xj = dXYZ4[rj];
        float dx = x0 - xj.x, dy = y0 - xj.y, dz = z0 - xj.z;
        float dis = sqrtf(dx * dx + dy * dy + dz * dz);

        // --- acc init = G (staged) ---
        ull acc[16];
        const ulonglong2* gsrc = (const ulonglong2*)(sw + lane * 68 + 32);
#pragma unroll
        for (int q = 0; q < 8; q++) {
            ulonglong2 v = gsrc[q];
            acc[2 * q] = v.x;
            acc[2 * q + 1] = v.y;
        }

        // --- fx + W3b matvec ---
        const float4* hsrc = (const float4*)(sw + lane * 68);
#pragma unroll
        for (int q = 0; q < 8; q++) {
            float4 h4 = hsrc[q];
            float hv[4] = {h4.x, h4.y, h4.z, h4.w};
#pragma unroll
            for (int e = 0; e < 4; e++) {
                int c = 4 * q + e;
                float fx = fmaxf(fmaf(sW1D[c], dis, base[c] + hv[e]), 0.0f);
                ull fx2 = pack2(fx, fx);
#pragma unroll
                for (int hq = 0; hq < 8; hq++) {
                    ulonglong2 w = sW3B2[c][hq];
                    acc[2 * hq] = ffma2(w.x, fx2, acc[2 * hq]);
                    acc[2 * hq + 1] = ffma2(w.y, fx2, acc[2 * hq + 1]);
                }
            }
        }

        // --- max pool ---
#pragma unroll
        for (int hp = 0; hp < 16; hp++) {
            float lo, hi;
            unpack2(acc[hp], lo, hi);
            fc[2 * hp] = fmaxf(fc[2 * hp], lo);
            fc[2 * hp + 1] = fmaxf(fc[2 * hp + 1], hi);
        }
    }

    // relu(max) == max(relu), store fc
    float* op = dFC + (size_t)p * HH;
#pragma unroll
    for (int q = 0; q < 8; q++)
        ((float4*)op)[q] = make_float4(fmaxf(fc[4 * q], 0.0f), fmaxf(fc[4 * q + 1], 0.0f),
                                       fmaxf(fc[4 * q + 2], 0.0f), fmaxf(fc[4 * q + 3], 0.0f));
}

// ================== pass 3: out = relu(W4' @ [fc; f] + b4) ==================
__global__ void __launch_bounds__(64) pass3_kernel(float* __restrict__ out) {
    __shared__ ull sW4[2 * HH][DD / 2];  // 16 KB
    __shared__ float sB4[DD];
    __shared__ float sFC[64 * 33];
    __shared__ float sF[64 * 33];
    int tid = threadIdx.x;
    for (int i = tid; i < 2 * HH * (DD / 2); i += 64) ((ull*)sW4)[i] = ((ull*)dW4P)[i];
    if (tid < DD) sB4[tid] = dB4[tid];
    int pbase = blockIdx.x * 64;
    for (int i = tid; i < 64 * HH; i += 64) {
        int r = i >> 5, c = i & 31;
        sFC[r * 33 + c] = dFC[(size_t)pbase * HH + i];
        sF[r * 33 + c] = dF[(size_t)pbase * HH + i];
    }
    __syncthreads();

    int p = pbase + tid;
    int b = p / NN;
    int n = p - b * NN;

    ull acc[DD / 2];
#pragma unroll
    for (int dp = 0; dp < 32; dp++) acc[dp] = pack2(sB4[2 * dp], sB4[2 * dp + 1]);
#pragma unroll
    for (int c = 0; c < HH; c++) {
        float v = sFC[tid * 33 + c];
        ull x2 = pack2(v, v);
        const ulonglong2* wr = (const ulonglong2*)sW4[c];
#pragma unroll
        for (int dq = 0; dq < 16; dq++) {
            ulonglong2 w = wr[dq];
            acc[2 * dq] = ffma2(w.x, x2, acc[2 * dq]);
            acc[2 * dq + 1] = ffma2(w.y, x2, acc[2 * dq + 1]);
        }
    }
#pragma unroll
    for (int c = 0; c < HH; c++) {
        float v = sF[tid * 33 + c];
        ull x2 = pack2(v, v);
        const ulonglong2* wr = (const ulonglong2*)sW4[HH + c];
#pragma unroll
        for (int dq = 0; dq < 16; dq++) {
            ulonglong2 w = wr[dq];
            acc[2 * dq] = ffma2(w.x, x2, acc[2 * dq]);
            acc[2 * dq + 1] = ffma2(w.y, x2, acc[2 * dq + 1]);
        }
    }
    float* op = out + (size_t)b * DD * NN + n;
#pragma unroll
    for (int dp = 0; dp < 32; dp++) {
        float lo, hi;
        unpack2(acc[dp], lo, hi);
        op[(size_t)(2 * dp) * NN] = fmaxf(lo, 0.0f);
        op[(size_t)(2 * dp + 1) * NN] = fmaxf(hi, 0.0f);
    }
}

// ================== launch ==================
extern "C" void kernel_launch(void* const* d_in, const int* in_sizes, int n_in,
                              void* d_out, int out_size) {
    const float *feat, *xyz, *W1, *W2, *W3, *W4;
    const float *g1, *b1, *g2, *b2, *g3, *b3, *g4, *b4;
    const void* idx;
    if (n_in >= 3 && in_sizes[2] == 320) {
        feat = (const float*)d_in[0];  xyz = (const float*)d_in[1];
        W1 = (const float*)d_in[2];    g1 = (const float*)d_in[3];  b1 = (const float*)d_in[4];
        W2 = (const float*)d_in[5];    g2 = (const float*)d_in[6];  b2 = (const float*)d_in[7];
        W3 = (const float*)d_in[8];    g3 = (const float*)d_in[9];  b3 = (const float*)d_in[10];
        W4 = (const float*)d_in[11];   g4 = (const float*)d_in[12]; b4 = (const float*)d_in[13];
        idx = d_in[14];
    } else {
        feat = (const float*)d_in[0];  xyz = (const float*)d_in[1];  idx = d_in[2];
        W1 = (const float*)d_in[3];    W2 = (const float*)d_in[4];
        W3 = (const float*)d_in[5];    W4 = (const float*)d_in[6];
        g1 = (const float*)d_in[7];    b1 = (const float*)d_in[8];
        g2 = (const float*)d_in[9];    b2 = (const float*)d_in[10];
        g3 = (const float*)d_in[11];   b3 = (const float*)d_in[12];
        g4 = (const float*)d_in[13];   b4 = (const float*)d_in[14];
    }
    prep_kernel<<<1, 256>>>(W1, W2, W3, W4, g1, b1, g2, b2, g3, b3, g4, b4);
    detect_kernel<<<1, 256>>>((const unsigned int*)idx);
    pass1_kernel<<<NPTS / 128, 128>>>(feat, xyz);
    pass2_kernel<<<NPTS / 128, 128>>>((const unsigned int*)idx);
    pass3_kernel<<<NPTS / 64, 64>>>((float*)d_out);
}